// round 16
// baseline (speedup 1.0000x reference)
#include <cuda_runtime.h>
#include <cuda_fp16.h>
#include <cstdint>

#define N_NODES  50000
#define N_REL    16
#define HID      128
#define N_LAYERS 3
#define N_EDGES  1600000
#define NSEG     (N_NODES * N_REL)   // 800000
#define KTOT     (N_REL * HID)       // 2048
#define NCHUNK   (N_REL + 1)         // 16 relations + root
#define W_ELEMS  (N_LAYERS * NCHUNK * 16384)
#define X_ELEMS  (N_NODES * HID)     // 6.4M

// ================= device scratch (no cudaMalloc allowed) =================
__device__ __align__(16) __half g_agg[(size_t)N_NODES * KTOT];   // 204.8 MB fp16
__device__ __align__(16) __half g_xh0[(size_t)X_ELEMS];  // fp16 node_init
__device__ __align__(16) __half g_xhA[(size_t)X_ELEMS];  // fp16 layer outputs
__device__ __align__(16) __half g_xhB[(size_t)X_ELEMS];
// weight stack: per layer 17 tiles of [n][k] fp16 (16 relations + root)
__device__ __align__(16) __half g_w[(size_t)W_ELEMS];
__device__ int g_cnt[NSEG];
__device__ int g_segstart[NSEG];  // block-local scan (finalize with blkoff)
__device__ int g_cursor[NSEG];
__device__ int g_blksum[1024];
__device__ int g_blkoff[1024];
__device__ int g_srcSorted[N_EDGES];
__device__ int g_worklist[NSEG];  // compacted non-empty segment ids
__device__ int g_nwork;

// ================= helpers =================
__device__ __forceinline__ uint32_t smem_to_u32(const void* p) {
    uint32_t a;
    asm("{ .reg .u64 t; cvta.to.shared.u64 t, %1; cvt.u32.u64 %0, t; }"
        : "=r"(a) : "l"(p));
    return a;
}
__device__ __forceinline__ void ldsm_x4(uint32_t* r, uint32_t addr) {
    asm volatile("ldmatrix.sync.aligned.m8n8.x4.shared.b16 {%0,%1,%2,%3}, [%4];"
        : "=r"(r[0]), "=r"(r[1]), "=r"(r[2]), "=r"(r[3]) : "r"(addr));
}
__device__ __forceinline__ void mma_f16(float* d, const uint32_t* a, const uint32_t* b) {
    asm volatile("mma.sync.aligned.m16n8k16.row.col.f32.f16.f16.f32 "
        "{%0,%1,%2,%3}, {%4,%5,%6,%7}, {%8,%9}, {%0,%1,%2,%3};"
        : "+f"(d[0]), "+f"(d[1]), "+f"(d[2]), "+f"(d[3])
        : "r"(a[0]), "r"(a[1]), "r"(a[2]), "r"(a[3]), "r"(b[0]), "r"(b[1]));
}
#define CP_ASYNC_16(dst, src, sz) \
    asm volatile("cp.async.cg.shared.global [%0], [%1], 16, %2;" \
                 :: "r"(dst), "l"(src), "r"(sz))
#define CP_ASYNC_COMMIT() asm volatile("cp.async.commit_group;" ::: "memory")
#define CP_ASYNC_WAIT0()  asm volatile("cp.async.wait_group 0;" ::: "memory")

__device__ __forceinline__ void acc8(float* s, uint4 r) {
    float2 f;
    f = __half22float2(*(__half2*)&r.x); s[0] += f.x; s[1] += f.y;
    f = __half22float2(*(__half2*)&r.y); s[2] += f.x; s[3] += f.y;
    f = __half22float2(*(__half2*)&r.z); s[4] += f.x; s[5] += f.y;
    f = __half22float2(*(__half2*)&r.w); s[6] += f.x; s[7] += f.y;
}

// ================= prep (6 launches) =======================================
// k1: zero counters + convert weights + convert node_init to fp16
__global__ void prep0_kernel(const float* __restrict__ W,
                             const float* __restrict__ root,
                             const float* __restrict__ x0) {
    int t = blockIdx.x * blockDim.x + threadIdx.x;
    if (t == 0) g_nwork = 0;
    if (t < NSEG) { g_cnt[t] = 0; g_cursor[t] = 0; }
    if (t < W_ELEMS) {
        int tt  = t >> 14;
        int rem = t & 16383;
        int n = rem >> 7;
        int k = rem & 127;
        int l = tt / NCHUNK;
        int c = tt % NCHUNK;
        float v;
        if (c < N_REL) v = W[(((size_t)l * N_REL + c) * HID + k) * HID + n];
        else           v = root[((size_t)l * HID + k) * HID + n];
        g_w[(size_t)tt * 16384 + n * HID + k] = __float2half_rn(v);
    }
    if (t < X_ELEMS) g_xh0[t] = __float2half_rn(x0[t]);
}
// k2: histogram only (edges re-read in bin)
__global__ void prep_edges_kernel(const int* __restrict__ edge_index,
                                  const int* __restrict__ edge_type) {
    int e = blockIdx.x * blockDim.x + threadIdx.x;
    if (e >= N_EDGES) return;
    int s = edge_index[e];
    int t = edge_index[N_EDGES + e];
    int r = edge_type[e];
    if ((unsigned)s >= N_NODES || (unsigned)t >= N_NODES || (unsigned)r >= N_REL)
        return;
    atomicAdd(&g_cnt[t * N_REL + r], 1);
}
__global__ void scan1_kernel() {
    __shared__ int s[256];
    int base = blockIdx.x * 1024;
    int t = threadIdx.x;
    int v[4]; int sum = 0;
    #pragma unroll
    for (int j = 0; j < 4; j++) {
        int idx = base + t * 4 + j;
        v[j] = (idx < NSEG) ? g_cnt[idx] : 0;
        sum += v[j];
    }
    s[t] = sum; __syncthreads();
    for (int off = 1; off < 256; off <<= 1) {
        int x = 0;
        if (t >= off) x = s[t - off];
        __syncthreads();
        if (t >= off) s[t] += x;
        __syncthreads();
    }
    int excl = (t > 0) ? s[t - 1] : 0;
    if (t == 255) g_blksum[blockIdx.x] = s[255];
    int run = excl;
    #pragma unroll
    for (int j = 0; j < 4; j++) {
        int idx = base + t * 4 + j;
        if (idx < NSEG) g_segstart[idx] = run;
        run += v[j];
    }
}
__global__ void scan2_kernel(int nb) {
    __shared__ int s[256];
    int t = threadIdx.x;
    int v[4]; int sum = 0;
    #pragma unroll
    for (int j = 0; j < 4; j++) {
        int idx = t * 4 + j;
        v[j] = (idx < nb) ? g_blksum[idx] : 0;
        sum += v[j];
    }
    s[t] = sum; __syncthreads();
    for (int off = 1; off < 256; off <<= 1) {
        int x = 0;
        if (t >= off) x = s[t - off];
        __syncthreads();
        if (t >= off) s[t] += x;
        __syncthreads();
    }
    int excl = (t > 0) ? s[t - 1] : 0;
    int run = excl;
    #pragma unroll
    for (int j = 0; j < 4; j++) {
        int idx = t * 4 + j;
        if (idx < nb) g_blkoff[idx] = run;
        run += v[j];
    }
}
// k-new: compact non-empty segments into worklist; zero agg rows of EMPTY
// segments once (agg never writes them, so they remain zero all layers).
__global__ void compact_kernel() {
    int i = blockIdx.x * blockDim.x + threadIdx.x;
    bool ne = (i < NSEG) && (g_cnt[i] > 0);
    unsigned mask = __ballot_sync(0xffffffffu, ne);
    int lane = threadIdx.x & 31;
    int base = 0;
    if (lane == 0 && mask) base = atomicAdd(&g_nwork, __popc(mask));
    base = __shfl_sync(0xffffffffu, base, 0);
    if (ne) {
        int pos = base + __popc(mask & ((1u << lane) - 1u));
        g_worklist[pos] = i;
    } else if (i < NSEG) {
        uint4 z = make_uint4(0, 0, 0, 0);
        uint4* dst = (uint4*)(g_agg + (size_t)i * HID);
        #pragma unroll
        for (int j = 0; j < 16; j++) dst[j] = z;
    }
}
// k5: counting-sort bin (recomputes seg/src from raw edges)
__global__ void bin_edges_kernel(const int* __restrict__ edge_index,
                                 const int* __restrict__ edge_type) {
    int e = blockIdx.x * blockDim.x + threadIdx.x;
    if (e >= N_EDGES) return;
    int s = edge_index[e];
    int t = edge_index[N_EDGES + e];
    int r = edge_type[e];
    if ((unsigned)s >= N_NODES || (unsigned)t >= N_NODES || (unsigned)r >= N_REL)
        return;
    int seg = t * N_REL + r;
    int base = g_segstart[seg] + g_blkoff[seg >> 10];
    int pos = base + atomicAdd(&g_cursor[seg], 1);
    g_srcSorted[pos] = s;
}

// ================= aggregation over non-empty segments only ================
// FOUR segments per warp: 8 lanes each, lane covers 32B of the 256B row
// (2x uint4). Edge loop 2-way unrolled -> 8 concurrent gather chains/warp.
__global__ __launch_bounds__(256) void agg_kernel(const __half* __restrict__ xh)
{
    int nwork = __ldg(&g_nwork);
    int g = (blockIdx.x * 256 + threadIdx.x) >> 3;   // one segment per 8 lanes
    if (g >= nwork) return;
    int seg  = __ldg(g_worklist + g);
    int lane = threadIdx.x & 7;
    int st = g_segstart[seg] + g_blkoff[seg >> 10];
    int c  = g_cnt[seg];

    float s[16];
    #pragma unroll
    for (int j = 0; j < 16; j++) s[j] = 0.f;

    int i = 0;
    for (; i + 2 <= c; i += 2) {
        int n0 = __ldg(g_srcSorted + st + i);
        int n1 = __ldg(g_srcSorted + st + i + 1);
        const uint4* r0 = (const uint4*)(xh + (size_t)n0 * HID) + lane * 2;
        const uint4* r1 = (const uint4*)(xh + (size_t)n1 * HID) + lane * 2;
        uint4 a0 = __ldg(r0), a1 = __ldg(r0 + 1);
        uint4 b0 = __ldg(r1), b1 = __ldg(r1 + 1);
        acc8(s, a0); acc8(s + 8, a1);
        acc8(s, b0); acc8(s + 8, b1);
    }
    if (i < c) {
        int n0 = __ldg(g_srcSorted + st + i);
        const uint4* r0 = (const uint4*)(xh + (size_t)n0 * HID) + lane * 2;
        uint4 a0 = __ldg(r0), a1 = __ldg(r0 + 1);
        acc8(s, a0); acc8(s + 8, a1);
    }
    float inv = 1.0f / (float)c;    // c > 0 guaranteed (worklist)
    __half2 p[8];
    #pragma unroll
    for (int j = 0; j < 8; j++)
        p[j] = __floats2half2_rn(s[2*j] * inv, s[2*j+1] * inv);
    size_t off = (size_t)seg * HID + lane * 16;
    asm volatile("st.global.cs.v4.b32 [%0], {%1,%2,%3,%4};"
                 :: "l"(g_agg + off),
                    "r"(*(uint32_t*)&p[0]), "r"(*(uint32_t*)&p[1]),
                    "r"(*(uint32_t*)&p[2]), "r"(*(uint32_t*)&p[3]) : "memory");
    asm volatile("st.global.cs.v4.b32 [%0], {%1,%2,%3,%4};"
                 :: "l"(g_agg + off + 8),
                    "r"(*(uint32_t*)&p[4]), "r"(*(uint32_t*)&p[5]),
                    "r"(*(uint32_t*)&p[6]), "r"(*(uint32_t*)&p[7]) : "memory");
}

// ================= layer GEMM: out = [agg | x] @ [Wstk; root] + bias =======
// K = 17 chunks x 128. 512 threads / 16 warps (32x32 warp tiles).
// cp.async pipeline: A double-buffered & prefetched behind MMA; B single.
#define TPAD      136
#define TILE_B    (128 * TPAD * 2)           // 34816 bytes
#define SM_A0     0
#define SM_A1     (SM_A0 + TILE_B)
#define SM_B      (SM_A1 + TILE_B)
#define SM_TOTAL  (SM_B + TILE_B)            // 104448

__global__ __launch_bounds__(512, 2) void rgcn_gemm(
    const __half* __restrict__ xh,           // fp16 activations (pre-activated)
    const __half* __restrict__ w,            // layer's 17-tile stack
    const float* __restrict__ bias,
    float* __restrict__ outf,                // final-layer fp32 out (or null)
    __half* __restrict__ outh,               // intermediate fp16 out (or null)
    int reluStore)
{
    extern __shared__ __align__(16) char smem[];
    const uint32_t sb = smem_to_u32(smem);
    const int tid  = threadIdx.x;
    const int wid  = tid >> 5;
    const int lane = tid & 31;
    const int rowBase = blockIdx.x * 128;

    const int mW = (wid & 3) * 32;
    const int nW = (wid >> 2) * 32;

    auto issueA = [&](int kc, uint32_t buf) {
        #pragma unroll
        for (int i = 0; i < 4; i++) {
            int idx4 = tid + i * 512;
            int row = idx4 >> 4, c16 = idx4 & 15;
            int gr = rowBase + row;
            const __half* src;
            if (kc < N_REL) src = g_agg + (size_t)gr * KTOT + (size_t)kc * HID + c16 * 8;
            else            src = xh + (size_t)gr * HID + c16 * 8;
            uint32_t sz = 16;
            if (gr >= N_NODES) { src = xh; sz = 0; }   // zero-fill OOB rows
            uint32_t dst = sb + buf + (uint32_t)row * (TPAD*2) + c16 * 16;
            CP_ASYNC_16(dst, src, sz);
        }
    };
    auto issueB = [&](int kc) {
        const __half* bw = w + (size_t)kc * 16384;
        #pragma unroll
        for (int i = 0; i < 4; i++) {
            int idx4 = tid + i * 512;
            int row = idx4 >> 4, c16 = idx4 & 15;
            uint32_t dst = sb + SM_B + (uint32_t)row * (TPAD*2) + c16 * 16;
            CP_ASYNC_16(dst, bw + row * HID + c16 * 8, 16);
        }
    };

    float acc[2][4][4];
    #pragma unroll
    for (int mt = 0; mt < 2; mt++)
        #pragma unroll
        for (int nt = 0; nt < 4; nt++)
            #pragma unroll
            for (int q = 0; q < 4; q++) acc[mt][nt][q] = 0.0f;

    // prologue: chunk 0 into A0 + B
    issueA(0, SM_A0);
    issueB(0);
    CP_ASYNC_COMMIT();
    CP_ASYNC_WAIT0();
    __syncthreads();

    for (int kc = 0; kc < NCHUNK; kc++) {
        const uint32_t aBase = sb + ((kc & 1) ? SM_A1 : SM_A0);

        if (kc + 1 < NCHUNK) {
            issueA(kc + 1, (kc & 1) ? SM_A0 : SM_A1);
            CP_ASYNC_COMMIT();
        }

        #pragma unroll
        for (int k0 = 0; k0 < HID; k0 += 16) {
            uint32_t a[2][4];
            {
                int ar = mW + (lane & 15);
                int ac = k0 + ((lane >> 4) << 3);
                ldsm_x4(a[0], aBase + (uint32_t)ar * (TPAD*2) + ac * 2);
                ldsm_x4(a[1], aBase + (uint32_t)(ar + 16) * (TPAD*2) + ac * 2);
            }
            uint32_t b[4][2];
            #pragma unroll
            for (int p = 0; p < 2; p++) {
                int g  = lane >> 3;
                int nn = nW + p * 16 + (lane & 7) + ((g >> 1) << 3);
                int kk = k0 + ((g & 1) << 3);
                uint32_t r[4];
                ldsm_x4(r, sb + SM_B + (uint32_t)nn * (TPAD*2) + kk * 2);
                b[p*2][0] = r[0]; b[p*2][1] = r[1];
                b[p*2+1][0] = r[2]; b[p*2+1][1] = r[3];
            }
            #pragma unroll
            for (int mt = 0; mt < 2; mt++)
                #pragma unroll
                for (int nt = 0; nt < 4; nt++)
                    mma_f16(acc[mt][nt], a[mt], b[nt]);
        }

        __syncthreads();
        if (kc + 1 < NCHUNK) {
            issueB(kc + 1);
            CP_ASYNC_COMMIT();
            CP_ASYNC_WAIT0();
            __syncthreads();
        }
    }

    // ---- epilogue: + bias (+ relu), store fp32 (final) or fp16 (interm) ----
    #pragma unroll
    for (int mt = 0; mt < 2; mt++) {
        int r0 = rowBase + mW + mt * 16 + (lane >> 2);
        int r1 = r0 + 8;
        #pragma unroll
        for (int nt = 0; nt < 4; nt++) {
            int col = nW + nt * 8 + (lane & 3) * 2;
            float b0 = bias[col], b1 = bias[col + 1];
            float v00 = acc[mt][nt][0] + b0, v01 = acc[mt][nt][1] + b1;
            float v10 = acc[mt][nt][2] + b0, v11 = acc[mt][nt][3] + b1;
            if (reluStore) {
                v00 = fmaxf(v00, 0.f); v01 = fmaxf(v01, 0.f);
                v10 = fmaxf(v10, 0.f); v11 = fmaxf(v11, 0.f);
            }
            if (outf) {
                if (r0 < N_NODES)
                    *(float2*)(outf + (size_t)r0 * HID + col) = make_float2(v00, v01);
                if (r1 < N_NODES)
                    *(float2*)(outf + (size_t)r1 * HID + col) = make_float2(v10, v11);
            } else {
                if (r0 < N_NODES) {
                    __half2 h = __floats2half2_rn(v00, v01);
                    *(uint32_t*)(outh + (size_t)r0 * HID + col) = *(uint32_t*)&h;
                }
                if (r1 < N_NODES) {
                    __half2 h = __floats2half2_rn(v10, v11);
                    *(uint32_t*)(outh + (size_t)r1 * HID + col) = *(uint32_t*)&h;
                }
            }
        }
    }
}

// ================= launch ================================================
extern "C" void kernel_launch(void* const* d_in, const int* in_sizes, int n_in,
                              void* d_out, int out_size)
{
    const int*   edge_index = (const int*)d_in[0];
    const int*   edge_type  = (const int*)d_in[1];
    const float* node_init  = (const float*)d_in[2];
    const float* W          = (const float*)d_in[3];
    const float* root       = (const float*)d_in[4];
    const float* bias       = (const float*)d_in[5];
    float*       out        = (float*)d_out;

    void* p;
    cudaGetSymbolAddress(&p, g_xh0); __half* xh0 = (__half*)p;
    cudaGetSymbolAddress(&p, g_xhA); __half* xhA = (__half*)p;
    cudaGetSymbolAddress(&p, g_xhB); __half* xhB = (__half*)p;
    cudaGetSymbolAddress(&p, g_w);   __half* w   = (__half*)p;

    cudaFuncSetAttribute(rgcn_gemm,
                         cudaFuncAttributeMaxDynamicSharedMemorySize, SM_TOTAL);

    const int scanBlocks = (NSEG + 1023) / 1024;   // 782
    prep0_kernel<<<(X_ELEMS + 255) / 256, 256>>>(W, root, node_init);
    prep_edges_kernel<<<(N_EDGES + 255) / 256, 256>>>(edge_index, edge_type);
    scan1_kernel<<<scanBlocks, 256>>>();
    scan2_kernel<<<1, 256>>>(scanBlocks);
    compact_kernel<<<(NSEG + 255) / 256, 256>>>();
    bin_edges_kernel<<<(N_EDGES + 255) / 256, 256>>>(edge_index, edge_type);

    const int rowTiles = (N_NODES + 127) / 128;    // 391
    const __half* xin = xh0;

    for (int l = 0; l < N_LAYERS; l++) {
        int last = (l == N_LAYERS - 1);
        __half* xoutH = last ? nullptr : (l == 0 ? xhA : xhB);
        float*  xoutF = last ? out : nullptr;
        int reluStore = last ? 0 : 1;
        // 4 segments per warp, 8 per 64 threads -> 32 per 256-thread block
        agg_kernel<<<(NSEG + 31) / 32, 256>>>(xin);
        rgcn_gemm<<<rowTiles, 512, SM_TOTAL>>>(
            xin, w + (size_t)l * NCHUNK * 16384,
            bias + (size_t)l * HID, xoutF, xoutH, reluStore);
        xin = xoutH;
    }
}